// round 7
// baseline (speedup 1.0000x reference)
#include <cuda_runtime.h>
#include <cstdint>
#include <math.h>

// ---------------------------------------------------------------------------
// SelectiveSSM, 3-kernel pipeline. B=4, L=1024, DM=64, DS=DI=128.
//   KA: block = 16 rows = 1 chunk. Software-pipelined over 4 groups of 4
//       rows: fused loop issues proj FMAs (group g+1) and exp MUFUs (group g)
//       from every warp so FMA and MUFU pipes run concurrently.
//       Epilogue: segment scan -> cc, ch, P, Q.
//   KB: 1 block: 64-chunk prefix scan of (P,Q) -> H.
//   KC: warp-per-row: y = sum_s(ch + cc*H), silu(gate), W_out GEMV,
//       residual, LayerNorm.
// ---------------------------------------------------------------------------

#define NB    4
#define NL    1024
#define NROW  4096
#define NCH   64
#define TC    16
#define LOG2E 1.4426950408889634f

__device__ float g_gate[NROW * 128];
__device__ float g_cc  [NROW * 128];
__device__ float g_ch  [NROW * 128];
__device__ float g_P   [NB * NCH * 128];
__device__ float g_Q   [NB * NCH * 128];
__device__ float g_H   [NB * NCH * 128];

__device__ __forceinline__ float ex2f(float v) {
    float r;
    asm("ex2.approx.ftz.f32 %0, %1;" : "=f"(r) : "f"(v));
    return r;
}
__device__ __forceinline__ float lg2f(float v) {
    float r;
    asm("lg2.approx.ftz.f32 %0, %1;" : "=f"(r) : "f"(v));
    return r;
}

// dynamic smem layout for KA (floats):
//   Asm[16384] | xs[1024] | dsm[2048] | bms[2048] | cs[2048] | abars[2048] |
//   segP[512] | segQ[512] | psum[512] | wpool[64] | pools[16]
#define KA_SMEM_FLOATS (16384 + 1024 + 2048 + 2048 + 2048 + 2048 + 512 + 512 + 512 + 64 + 16)

// ---------------------------------------------------------------------------
// KA: 256 blocks x 512 threads, 2 blocks/SM. smem ~106KB.
// ---------------------------------------------------------------------------
__global__ __launch_bounds__(512, 2) void ka(
    const float* __restrict__ x,   const float* __restrict__ Win,
    const float* __restrict__ Wd,  const float* __restrict__ bd,
    const float* __restrict__ WB,  const float* __restrict__ bB,
    const float* __restrict__ WC,  const float* __restrict__ bC,
    const float* __restrict__ A) {
    extern __shared__ __align__(16) float sm[];
    float* Asm   = sm;                 // 128x128, raw A
    float* xs    = Asm + 16384;        // 16x64
    float* dsm   = xs + 1024;          // 16x128 delta*log2e
    float* bms   = dsm + 2048;
    float* cs    = bms + 2048;
    float* abars = cs + 2048;          // 16x128 Abar
    float* segP  = abars + 2048;
    float* segQ  = segP + 512;
    float* psum  = segQ + 512;
    float* wpool = psum + 512;
    float* pools = wpool + 64;

    int tid = threadIdx.x;
    int row0 = blockIdx.x * TC;

    // ---- phase 0: stage A, x rows, wpool partials
    {
        const float4* A4 = (const float4*)A;
        float4* Asm4 = (float4*)Asm;
        for (int i = tid; i < 4096; i += 512) Asm4[i] = A4[i];
    }
    for (int i = tid; i < TC * 64; i += 512) xs[i] = x[row0 * 64 + i];
    {
        int d = tid & 63, part = tid >> 6;
        float s = 0.f;
        const float* p = Win + part * 16 * 64 + d;
#pragma unroll
        for (int i = 0; i < 16; i++) s += p[i * 64];
        psum[part * 64 + d] = s;
    }
    __syncthreads();

    if (tid < 64) {
        float s = 0.f;
#pragma unroll
        for (int p = 0; p < 8; p++) s += psum[p * 64 + tid];
        wpool[tid] = s * (1.0f / 128.0f);
    }

    // ---- proj setup (thread = feature)
    int mode = tid >> 7, fo = tid & 127;
    const float* wrow;
    float bias = 0.f;
    if (mode == 0)      { wrow = Win + (128 + fo) * 64; }
    else if (mode == 1) { wrow = Wd + fo * 64; bias = bd[fo]; }
    else if (mode == 2) { wrow = WB + fo * 64; bias = bB[fo]; }
    else                { wrow = WC + fo * 64; bias = bC[fo]; }
    const float4* w4 = (const float4*)wrow;

    // ---- prologue: project group 0 (rows 0..3)
    {
        float acc[4] = {0.f, 0.f, 0.f, 0.f};
#pragma unroll
        for (int d4 = 0; d4 < 16; d4++) {
            float4 wv = __ldg(&w4[d4]);
#pragma unroll
            for (int r = 0; r < 4; r++) {
                float4 xv = *(const float4*)(xs + r * 64 + d4 * 4);
                acc[r] = fmaf(wv.x, xv.x, acc[r]);
                acc[r] = fmaf(wv.y, xv.y, acc[r]);
                acc[r] = fmaf(wv.z, xv.z, acc[r]);
                acc[r] = fmaf(wv.w, xv.w, acc[r]);
            }
        }
#pragma unroll
        for (int r = 0; r < 4; r++) {
            float v = acc[r] + bias;
            if (mode == 0)      g_gate[(row0 + r) * 128 + fo] = v;
            else if (mode == 1) dsm[r * 128 + fo] = lg2f(1.0f + ex2f(v * LOG2E));
            else if (mode == 2) bms[r * 128 + fo] = v;
            else                cs [r * 128 + fo] = v;
        }
    }
    __syncthreads();

    // x_pool (wpool ready; pools consumed after later barriers)
    if (tid < TC) {
        float p = 0.f;
#pragma unroll
        for (int d = 0; d < 64; d++) p = fmaf(wpool[d], xs[tid * 64 + d], p);
        pools[tid] = p;
    }

    // ---- fused pipeline: exp(group g) + proj(group g+1)
    int s = tid & 127, rp = tid >> 7;     // exp role: row rg = g*4 + rp
#pragma unroll
    for (int g = 0; g < 4; g++) {
        int rg = g * 4 + rp;
        const float* dr = dsm + rg * 128;
        float acc[4] = {0.f, 0.f, 0.f, 0.f};
        float sg = 0.f;
#pragma unroll 4
        for (int ii = 0; ii < 16; ii++) {
            // proj slice for group g+1 (compile-time dead for g==3)
            if (g < 3) {
                float4 wv = __ldg(&w4[ii]);
#pragma unroll
                for (int r = 0; r < 4; r++) {
                    float4 xv = *(const float4*)(xs + ((g + 1) * 4 + r) * 64 + ii * 4);
                    acc[r] = fmaf(wv.x, xv.x, acc[r]);
                    acc[r] = fmaf(wv.y, xv.y, acc[r]);
                    acc[r] = fmaf(wv.z, xv.z, acc[r]);
                    acc[r] = fmaf(wv.w, xv.w, acc[r]);
                }
            }
            // exp slice: 8 states of inner dim
            float4 qa = *(const float4*)(dr + ii * 8);
            float4 qb = *(const float4*)(dr + ii * 8 + 4);
            float A0 = Asm[(ii * 8 + 0) * 128 + s];
            float A1 = Asm[(ii * 8 + 1) * 128 + s];
            float A2 = Asm[(ii * 8 + 2) * 128 + s];
            float A3 = Asm[(ii * 8 + 3) * 128 + s];
            float A4v = Asm[(ii * 8 + 4) * 128 + s];
            float A5 = Asm[(ii * 8 + 5) * 128 + s];
            float A6 = Asm[(ii * 8 + 6) * 128 + s];
            float A7 = Asm[(ii * 8 + 7) * 128 + s];
            sg += (ex2f(qa.x * A0) + ex2f(qa.y * A1)) + (ex2f(qa.z * A2) + ex2f(qa.w * A3));
            sg += (ex2f(qb.x * A4v) + ex2f(qb.y * A5)) + (ex2f(qb.z * A6) + ex2f(qb.w * A7));
        }
        abars[rg * 128 + s] = sg * (1.0f / 128.0f);
        if (g < 3) {
#pragma unroll
            for (int r = 0; r < 4; r++) {
                int rr = (g + 1) * 4 + r;
                float v = acc[r] + bias;
                if (mode == 0)      g_gate[(row0 + rr) * 128 + fo] = v;
                else if (mode == 1) dsm[rr * 128 + fo] = lg2f(1.0f + ex2f(v * LOG2E));
                else if (mode == 2) bms[rr * 128 + fo] = v;
                else                cs [rr * 128 + fo] = v;
            }
        }
        __syncthreads();
    }

    // ---- scan epilogue: thread (s, rq) owns timesteps rq*4..rq*4+3
    int rq = rp;
    float a[4], bp[4];
    {
        float h = 0.f, cA = 1.f;
#pragma unroll
        for (int k = 0; k < 4; k++) {
            int t = rq * 4 + k;
            a[k] = abars[t * 128 + s];
            bp[k] = bms[t * 128 + s] * pools[t];
            h = fmaf(a[k], h, bp[k]);
            cA *= a[k];
        }
        segP[rq * 128 + s] = cA;
        segQ[rq * 128 + s] = h;
    }
    __syncthreads();
    {
        float Pp = 1.f, h = 0.f;
#pragma unroll
        for (int j = 0; j < 3; j++) {
            if (j < rq) {
                float pj = segP[j * 128 + s];
                h = fmaf(pj, h, segQ[j * 128 + s]);
                Pp *= pj;
            }
        }
#pragma unroll
        for (int k = 0; k < 4; k++) {
            int t = rq * 4 + k;
            h = fmaf(a[k], h, bp[k]);
            Pp *= a[k];
            float c = cs[t * 128 + s];
            int off = (row0 + t) * 128 + s;
            g_cc[off] = c * Pp;
            g_ch[off] = c * h;
        }
        if (rq == 3) {
            g_P[blockIdx.x * 128 + s] = Pp;
            g_Q[blockIdx.x * 128 + s] = h;
        }
    }
}

// ---------------------------------------------------------------------------
// KB: 1 block, 512 threads: (b = tid>>7, s = tid&127), 64-chunk serial scan.
// ---------------------------------------------------------------------------
__global__ void kb() {
    int tid = threadIdx.x;
    int b = tid >> 7, s = tid & 127;
    int o0 = b * NCH * 128 + s;
    float P[2][8], Q[2][8];
#pragma unroll
    for (int j = 0; j < 8; j++) {
        P[0][j] = g_P[o0 + j * 128];
        Q[0][j] = g_Q[o0 + j * 128];
    }
    float H = 0.f;
    for (int T = 0; T < 8; T++) {
        int cur = T & 1, nxt = cur ^ 1;
        if (T < 7) {
#pragma unroll
            for (int j = 0; j < 8; j++) {
                int o = o0 + ((T + 1) * 8 + j) * 128;
                P[nxt][j] = g_P[o];
                Q[nxt][j] = g_Q[o];
            }
        }
#pragma unroll
        for (int j = 0; j < 8; j++) {
            g_H[o0 + (T * 8 + j) * 128] = H;
            H = fmaf(P[cur][j], H, Q[cur][j]);
        }
    }
}

// ---------------------------------------------------------------------------
// KC: 256 blocks x 512 threads, warp-per-row.
// ---------------------------------------------------------------------------
__global__ __launch_bounds__(512) void kc(const float* __restrict__ x,
                                          const float* __restrict__ Wout,
                                          const float* __restrict__ lnw,
                                          const float* __restrict__ lnb,
                                          float* __restrict__ out) {
    __shared__ float WT2s[128 * 65];
    __shared__ float yis[TC * 128];
    __shared__ float Hs[128];
    int tid = threadIdx.x, lane = tid & 31, w = tid >> 5;
    int row0 = blockIdx.x * TC;

    for (int lin = tid; lin < 8192; lin += 512) {
        int d = lin >> 7, ii = lin & 127;
        WT2s[ii * 65 + d] = Wout[lin];
    }
    if (tid < 128) Hs[tid] = g_H[blockIdx.x * 128 + tid];
    __syncthreads();

    int row = row0 + w;
    {
        float acc = 0.f;
        float gt[4];
#pragma unroll
        for (int q = 0; q < 4; q++) {
            int s = lane + q * 32;
            int off = row * 128 + s;
            acc += g_ch[off] + g_cc[off] * Hs[s];
            gt[q] = g_gate[off];
        }
#pragma unroll
        for (int o = 16; o > 0; o >>= 1) acc += __shfl_xor_sync(0xffffffffu, acc, o);
#pragma unroll
        for (int q = 0; q < 4; q++) {
            int s = lane + q * 32;
            float sig = 1.0f / (1.0f + __expf(-gt[q]));
            yis[w * 128 + s] = acc * gt[q] * sig;
        }
    }
    __syncthreads();

    {
        float acc0 = 0.f, acc1 = 0.f;
#pragma unroll 8
        for (int i = 0; i < 128; i++) {
            float yv = yis[w * 128 + i];
            acc0 = fmaf(WT2s[i * 65 + lane],      yv, acc0);
            acc1 = fmaf(WT2s[i * 65 + lane + 32], yv, acc1);
        }
        float v0 = acc0 + x[row * 64 + lane];
        float v1 = acc1 + x[row * 64 + lane + 32];
        float sv = v0 + v1, sq = v0 * v0 + v1 * v1;
#pragma unroll
        for (int o = 16; o > 0; o >>= 1) {
            sv += __shfl_xor_sync(0xffffffffu, sv, o);
            sq += __shfl_xor_sync(0xffffffffu, sq, o);
        }
        float mu  = sv * (1.0f / 64.0f);
        float var = sq * (1.0f / 64.0f) - mu * mu;
        float inv = rsqrtf(var + 1e-5f);
        out[row * 64 + lane]      = (v0 - mu) * inv * lnw[lane]      + lnb[lane];
        out[row * 64 + lane + 32] = (v1 - mu) * inv * lnw[lane + 32] + lnb[lane + 32];
    }
}

// ---------------------------------------------------------------------------
extern "C" void kernel_launch(void* const* d_in, const int* in_sizes, int n_in,
                              void* d_out, int out_size) {
    const float* x    = (const float*)d_in[0];
    const float* Win  = (const float*)d_in[1];
    const float* Wd   = (const float*)d_in[2];
    const float* bd   = (const float*)d_in[3];
    const float* WB   = (const float*)d_in[4];
    const float* bB   = (const float*)d_in[5];
    const float* WC   = (const float*)d_in[6];
    const float* bC   = (const float*)d_in[7];
    const float* A    = (const float*)d_in[8];
    const float* Wout = (const float*)d_in[9];
    const float* lnw  = (const float*)d_in[10];
    const float* lnb  = (const float*)d_in[11];
    float* out = (float*)d_out;

    cudaFuncSetAttribute(ka, cudaFuncAttributeMaxDynamicSharedMemorySize,
                         KA_SMEM_FLOATS * (int)sizeof(float));

    ka<<<NROW / TC, 512, KA_SMEM_FLOATS * sizeof(float)>>>(
        x, Win, Wd, bd, WB, bB, WC, bC, A);
    kb<<<1, 512>>>();
    kc<<<NROW / TC, 512>>>(x, Wout, lnw, lnb, out);
}

// round 8
// speedup vs baseline: 1.4603x; 1.4603x over previous
#include <cuda_runtime.h>
#include <cstdint>
#include <math.h>

// ---------------------------------------------------------------------------
// SelectiveSSM, 4-kernel pipe-split pipeline. B=4, L=1024, DM=64, DS=DI=128.
//   KP: projections only (pure FMA pipe): gate, delta*log2e, Bm, Cm, x_pool.
//   KE: exp sums (pure MUFU) + chunk segment scan -> cc, ch, P, Q.
//   KB: 1 block: 64-chunk prefix scan of (P,Q) -> H.
//   KC: warp-per-row: y = sum_s(ch + cc*H), silu(gate), W_out GEMV,
//       residual, LayerNorm.
// Rationale: proj->exp dependency phase-locks FMA and MUFU inside one kernel
// (16.4K idle MUFU cyc/block). Split kernels each saturate their own pipe.
// ---------------------------------------------------------------------------

#define NB    4
#define NL    1024
#define NROW  4096
#define NCH   64
#define TC    16
#define LOG2E 1.4426950408889634f

__device__ float g_gate [NROW * 128];
__device__ float g_delta[NROW * 128];   // delta * log2e
__device__ float g_bm   [NROW * 128];
__device__ float g_c    [NROW * 128];
__device__ float g_pool [NROW];
__device__ float g_cc   [NROW * 128];
__device__ float g_ch   [NROW * 128];
__device__ float g_P    [NB * NCH * 128];
__device__ float g_Q    [NB * NCH * 128];
__device__ float g_H    [NB * NCH * 128];

__device__ __forceinline__ float ex2f(float v) {
    float r;
    asm("ex2.approx.ftz.f32 %0, %1;" : "=f"(r) : "f"(v));
    return r;
}
__device__ __forceinline__ float lg2f(float v) {
    float r;
    asm("lg2.approx.ftz.f32 %0, %1;" : "=f"(r) : "f"(v));
    return r;
}

// ---------------------------------------------------------------------------
// KP: 256 blocks x 512 threads. Pure-FMA projections. smem ~4.3KB -> high occ.
// ---------------------------------------------------------------------------
__global__ __launch_bounds__(512) void kp(
    const float* __restrict__ x,   const float* __restrict__ Win,
    const float* __restrict__ Wd,  const float* __restrict__ bd,
    const float* __restrict__ WB,  const float* __restrict__ bB,
    const float* __restrict__ WC,  const float* __restrict__ bC) {
    __shared__ __align__(16) float xs[TC * 64];
    __shared__ float psum[8 * 64];
    __shared__ float wpool[64];

    int tid = threadIdx.x;
    int row0 = blockIdx.x * TC;

    for (int i = tid; i < TC * 64; i += 512) xs[i] = x[row0 * 64 + i];
    {
        int d = tid & 63, part = tid >> 6;
        float s = 0.f;
        const float* p = Win + part * 16 * 64 + d;
#pragma unroll
        for (int i = 0; i < 16; i++) s += p[i * 64];
        psum[part * 64 + d] = s;
    }
    __syncthreads();

    if (tid < 64) {
        float s = 0.f;
#pragma unroll
        for (int p = 0; p < 8; p++) s += psum[p * 64 + tid];
        wpool[tid] = s * (1.0f / 128.0f);
    }

    int mode = tid >> 7, fo = tid & 127;
    const float* wrow;
    float bias = 0.f;
    if (mode == 0)      { wrow = Win + (128 + fo) * 64; }
    else if (mode == 1) { wrow = Wd + fo * 64; bias = bd[fo]; }
    else if (mode == 2) { wrow = WB + fo * 64; bias = bB[fo]; }
    else                { wrow = WC + fo * 64; bias = bC[fo]; }
    const float4* w4 = (const float4*)wrow;

    float acc[TC];
#pragma unroll
    for (int r = 0; r < TC; r++) acc[r] = 0.f;
#pragma unroll
    for (int d4 = 0; d4 < 16; d4++) {
        float4 wv = __ldg(&w4[d4]);
#pragma unroll
        for (int r = 0; r < TC; r++) {
            float4 xv = *(const float4*)(xs + r * 64 + d4 * 4);
            acc[r] = fmaf(wv.x, xv.x, acc[r]);
            acc[r] = fmaf(wv.y, xv.y, acc[r]);
            acc[r] = fmaf(wv.z, xv.z, acc[r]);
            acc[r] = fmaf(wv.w, xv.w, acc[r]);
        }
    }
#pragma unroll
    for (int r = 0; r < TC; r++) {
        float v = acc[r] + bias;
        int o = (row0 + r) * 128 + fo;
        if (mode == 0)      g_gate[o] = v;
        else if (mode == 1) g_delta[o] = lg2f(1.0f + ex2f(v * LOG2E));  // δ·log2e
        else if (mode == 2) g_bm[o] = v;
        else                g_c [o] = v;
    }
    __syncthreads();   // wpool ready

    if (tid < TC) {
        float p = 0.f;
#pragma unroll
        for (int d = 0; d < 64; d++) p = fmaf(wpool[d], xs[tid * 64 + d], p);
        g_pool[row0 + tid] = p;
    }
}

// ---------------------------------------------------------------------------
// KE: 256 blocks x 512 threads, 2 blocks/SM. MUFU-bound exp + segment scan.
//   dynamic smem: Asm[16384] | dsm[2048] | segP[512] | segQ[512]  (~76KB)
// ---------------------------------------------------------------------------
#define KE_SMEM_FLOATS (16384 + 2048 + 512 + 512)

__global__ __launch_bounds__(512, 2) void ke(const float* __restrict__ A) {
    extern __shared__ __align__(16) float sm[];
    float* Asm  = sm;            // 128x128 raw A
    float* dsm  = Asm + 16384;   // 16x128 delta*log2e
    float* segP = dsm + 2048;
    float* segQ = segP + 512;

    int tid = threadIdx.x;
    int row0 = blockIdx.x * TC;

    {
        const float4* A4 = (const float4*)A;
        float4* Asm4 = (float4*)Asm;
        for (int i = tid; i < 4096; i += 512) Asm4[i] = A4[i];
    }
    {
        const float4* D4 = (const float4*)(g_delta + row0 * 128);
        float4* dsm4 = (float4*)dsm;
        for (int i = tid; i < 512; i += 512) dsm4[i] = D4[i];
    }
    __syncthreads();

    // exp sums: thread (s, rq) owns rows rq*4..rq*4+3
    int s = tid & 127, rq = tid >> 7;
    float a[4];
    {
        const float* dr = dsm + rq * 4 * 128;
        float s0 = 0.f, s1 = 0.f, s2 = 0.f, s3 = 0.f;
#pragma unroll 4
        for (int i = 0; i < 128; i += 4) {
            float4 q0 = *(const float4*)(dr + i);
            float4 q1 = *(const float4*)(dr + 128 + i);
            float4 q2 = *(const float4*)(dr + 256 + i);
            float4 q3 = *(const float4*)(dr + 384 + i);
            float A0 = Asm[(i + 0) * 128 + s];
            float A1 = Asm[(i + 1) * 128 + s];
            float A2 = Asm[(i + 2) * 128 + s];
            float A3 = Asm[(i + 3) * 128 + s];
            s0 += (ex2f(q0.x * A0) + ex2f(q0.y * A1)) + (ex2f(q0.z * A2) + ex2f(q0.w * A3));
            s1 += (ex2f(q1.x * A0) + ex2f(q1.y * A1)) + (ex2f(q1.z * A2) + ex2f(q1.w * A3));
            s2 += (ex2f(q2.x * A0) + ex2f(q2.y * A1)) + (ex2f(q2.z * A2) + ex2f(q2.w * A3));
            s3 += (ex2f(q3.x * A0) + ex2f(q3.y * A1)) + (ex2f(q3.z * A2) + ex2f(q3.w * A3));
        }
        a[0] = s0 * (1.0f / 128.0f);
        a[1] = s1 * (1.0f / 128.0f);
        a[2] = s2 * (1.0f / 128.0f);
        a[3] = s3 * (1.0f / 128.0f);
    }

    // segment scan over this thread's 4 timesteps (bm/c/pool from global)
    float bp[4];
    {
        float h = 0.f, cA = 1.f;
#pragma unroll
        for (int k = 0; k < 4; k++) {
            int t = rq * 4 + k;
            bp[k] = g_bm[(row0 + t) * 128 + s] * g_pool[row0 + t];
            h = fmaf(a[k], h, bp[k]);
            cA *= a[k];
        }
        segP[rq * 128 + s] = cA;
        segQ[rq * 128 + s] = h;
    }
    __syncthreads();

    // fold preceding segments, emit cc/ch
    {
        float Pp = 1.f, h = 0.f;
#pragma unroll
        for (int j = 0; j < 3; j++) {
            if (j < rq) {
                float pj = segP[j * 128 + s];
                h = fmaf(pj, h, segQ[j * 128 + s]);
                Pp *= pj;
            }
        }
#pragma unroll
        for (int k = 0; k < 4; k++) {
            int t = rq * 4 + k;
            h = fmaf(a[k], h, bp[k]);
            Pp *= a[k];
            float c = g_c[(row0 + t) * 128 + s];
            int off = (row0 + t) * 128 + s;
            g_cc[off] = c * Pp;
            g_ch[off] = c * h;
        }
        if (rq == 3) {
            g_P[blockIdx.x * 128 + s] = Pp;
            g_Q[blockIdx.x * 128 + s] = h;
        }
    }
}

// ---------------------------------------------------------------------------
// KB: 1 block, 512 threads: 64-chunk serial prefix scan.
// ---------------------------------------------------------------------------
__global__ void kb() {
    int tid = threadIdx.x;
    int b = tid >> 7, s = tid & 127;
    int o0 = b * NCH * 128 + s;
    float P[2][8], Q[2][8];
#pragma unroll
    for (int j = 0; j < 8; j++) {
        P[0][j] = g_P[o0 + j * 128];
        Q[0][j] = g_Q[o0 + j * 128];
    }
    float H = 0.f;
    for (int T = 0; T < 8; T++) {
        int cur = T & 1, nxt = cur ^ 1;
        if (T < 7) {
#pragma unroll
            for (int j = 0; j < 8; j++) {
                int o = o0 + ((T + 1) * 8 + j) * 128;
                P[nxt][j] = g_P[o];
                Q[nxt][j] = g_Q[o];
            }
        }
#pragma unroll
        for (int j = 0; j < 8; j++) {
            g_H[o0 + (T * 8 + j) * 128] = H;
            H = fmaf(P[cur][j], H, Q[cur][j]);
        }
    }
}

// ---------------------------------------------------------------------------
// KC: 256 blocks x 512 threads, warp-per-row.
// ---------------------------------------------------------------------------
__global__ __launch_bounds__(512) void kc(const float* __restrict__ x,
                                          const float* __restrict__ Wout,
                                          const float* __restrict__ lnw,
                                          const float* __restrict__ lnb,
                                          float* __restrict__ out) {
    __shared__ float WT2s[128 * 65];
    __shared__ float yis[TC * 128];
    __shared__ float Hs[128];
    int tid = threadIdx.x, lane = tid & 31, w = tid >> 5;
    int row0 = blockIdx.x * TC;

    for (int lin = tid; lin < 8192; lin += 512) {
        int d = lin >> 7, ii = lin & 127;
        WT2s[ii * 65 + d] = Wout[lin];
    }
    if (tid < 128) Hs[tid] = g_H[blockIdx.x * 128 + tid];
    __syncthreads();

    int row = row0 + w;
    {
        float acc = 0.f;
        float gt[4];
#pragma unroll
        for (int q = 0; q < 4; q++) {
            int s = lane + q * 32;
            int off = row * 128 + s;
            acc += g_ch[off] + g_cc[off] * Hs[s];
            gt[q] = g_gate[off];
        }
#pragma unroll
        for (int o = 16; o > 0; o >>= 1) acc += __shfl_xor_sync(0xffffffffu, acc, o);
#pragma unroll
        for (int q = 0; q < 4; q++) {
            int s = lane + q * 32;
            float sig = 1.0f / (1.0f + __expf(-gt[q]));
            yis[w * 128 + s] = acc * gt[q] * sig;
        }
    }
    __syncthreads();

    {
        float acc0 = 0.f, acc1 = 0.f;
#pragma unroll 8
        for (int i = 0; i < 128; i++) {
            float yv = yis[w * 128 + i];
            acc0 = fmaf(WT2s[i * 65 + lane],      yv, acc0);
            acc1 = fmaf(WT2s[i * 65 + lane + 32], yv, acc1);
        }
        float v0 = acc0 + x[row * 64 + lane];
        float v1 = acc1 + x[row * 64 + lane + 32];
        float sv = v0 + v1, sq = v0 * v0 + v1 * v1;
#pragma unroll
        for (int o = 16; o > 0; o >>= 1) {
            sv += __shfl_xor_sync(0xffffffffu, sv, o);
            sq += __shfl_xor_sync(0xffffffffu, sq, o);
        }
        float mu  = sv * (1.0f / 64.0f);
        float var = sq * (1.0f / 64.0f) - mu * mu;
        float inv = rsqrtf(var + 1e-5f);
        out[row * 64 + lane]      = (v0 - mu) * inv * lnw[lane]      + lnb[lane];
        out[row * 64 + lane + 32] = (v1 - mu) * inv * lnw[lane + 32] + lnb[lane + 32];
    }
}

// ---------------------------------------------------------------------------
extern "C" void kernel_launch(void* const* d_in, const int* in_sizes, int n_in,
                              void* d_out, int out_size) {
    const float* x    = (const float*)d_in[0];
    const float* Win  = (const float*)d_in[1];
    const float* Wd   = (const float*)d_in[2];
    const float* bd   = (const float*)d_in[3];
    const float* WB   = (const float*)d_in[4];
    const float* bB   = (const float*)d_in[5];
    const float* WC   = (const float*)d_in[6];
    const float* bC   = (const float*)d_in[7];
    const float* A    = (const float*)d_in[8];
    const float* Wout = (const float*)d_in[9];
    const float* lnw  = (const float*)d_in[10];
    const float* lnb  = (const float*)d_in[11];
    float* out = (float*)d_out;

    cudaFuncSetAttribute(ke, cudaFuncAttributeMaxDynamicSharedMemorySize,
                         KE_SMEM_FLOATS * (int)sizeof(float));

    kp<<<NROW / TC, 512>>>(x, Win, Wd, bd, WB, bB, WC, bC);
    ke<<<NROW / TC, 512, KE_SMEM_FLOATS * sizeof(float)>>>(A);
    kb<<<1, 512>>>();
    kc<<<NROW / TC, 512>>>(x, Wout, lnw, lnb, out);
}